// round 3
// baseline (speedup 1.0000x reference)
#include <cuda_runtime.h>
#include <cstdint>

#define NN 50000
#define NE 800000
#define DIM 128
#define TOT (NN * DIM)            // 6,400,000
#define MASK_WORDS (TOT / 32)     // 200,000

// ---------------- scratch (no allocation allowed) ----------------
__device__ float g_h[TOT];        // lin(x) output per layer
__device__ float g_agg[TOT];      // scatter accumulator / mlp1 scratch
__device__ float g_x1[TOT];       // layer-1 output
__device__ float g_x2[TOT];       // layer-2 output
__device__ float g_deg[NN];       // degree -> inverse degree
__device__ unsigned g_mask[3][MASK_WORDS];
__device__ int g_row[NE];
__device__ int g_col[NE];
__device__ int g_is64;            // 1 if edge_index buffer is int64

// ---------------- threefry2x32 (exact JAX semantics) ----------------
__host__ __device__ __forceinline__ void threefry2x32(
    unsigned k0, unsigned k1, unsigned x0, unsigned x1,
    unsigned& y0, unsigned& y1)
{
    unsigned ks0 = k0, ks1 = k1, ks2 = k0 ^ k1 ^ 0x1BD11BDAu;
#define TF_R(r) { x0 += x1; x1 = (x1 << (r)) | (x1 >> (32 - (r))); x1 ^= x0; }
    x0 += ks0; x1 += ks1;
    TF_R(13) TF_R(15) TF_R(26) TF_R(6)
    x0 += ks1; x1 += ks2 + 1u;
    TF_R(17) TF_R(29) TF_R(16) TF_R(24)
    x0 += ks2; x1 += ks0 + 2u;
    TF_R(13) TF_R(15) TF_R(26) TF_R(6)
    x0 += ks0; x1 += ks1 + 3u;
    TF_R(17) TF_R(29) TF_R(16) TF_R(24)
    x0 += ks1; x1 += ks2 + 4u;
    TF_R(13) TF_R(15) TF_R(26) TF_R(6)
    y0 = x0 + ks2; y1 = x1 + ks0 + 5u;
#undef TF_R
}

// ---------------- edge-index dtype detect + unpack ----------------
// int64 node ids are < 50000 => every odd 32-bit word (high half) of the
// buffer is 0. For int32 data those words are random node ids.
__global__ void detect_kernel(const unsigned* __restrict__ raw)
{
    __shared__ int any;
    if (threadIdx.x == 0) any = 0;
    __syncthreads();
    unsigned w = raw[threadIdx.x * 2 + 1];     // first 8KB only: safe either way
    if (w != 0u) atomicOr(&any, 1);
    __syncthreads();
    if (threadIdx.x == 0) g_is64 = (any == 0) ? 1 : 0;
}

__global__ void unpack_kernel(const void* __restrict__ raw)
{
    int e = blockIdx.x * blockDim.x + threadIdx.x;
    if (e >= 2 * NE) return;
    int v;
    if (g_is64) v = (int)((const long long*)raw)[e];
    else        v = ((const int*)raw)[e];
    if (e < NE) g_row[e] = v;
    else        g_col[e - NE] = v;
}

// JAX partitionable threefry random_bits(32): element j uses 64-bit counter j
// as block (hi=0, lo=j); output word = y0 ^ y1. bernoulli(0.5) keeps iff
// uniform<0.5 iff MSB of bits is 0.
__global__ void mask_kernel(unsigned ka, unsigned kb, int layer)
{
    unsigned j = blockIdx.x * blockDim.x + threadIdx.x;   // 0..TOT-1 exactly
    unsigned y0, y1;
    threefry2x32(ka, kb, 0u, j, y0, y1);
    unsigned bits = y0 ^ y1;
    unsigned keep = (bits >> 31) ^ 1u;
    unsigned w = __ballot_sync(0xffffffffu, keep);
    if ((threadIdx.x & 31) == 0) g_mask[layer][j >> 5] = w;
}

// ---------------- degree ----------------
__global__ void zero_deg_kernel()
{
    int i = blockIdx.x * blockDim.x + threadIdx.x;
    if (i < NN) g_deg[i] = 0.0f;
}
__global__ void deg_kernel()
{
    int e = blockIdx.x * blockDim.x + threadIdx.x;
    if (e < NE) atomicAdd(&g_deg[g_row[e]], 1.0f);
}
__global__ void inv_kernel()
{
    int i = blockIdx.x * blockDim.x + threadIdx.x;
    if (i < NN) g_deg[i] = 1.0f / fmaxf(g_deg[i], 1.0f);
}
__global__ void zero4_kernel(float4* p, int n4)
{
    int i = blockIdx.x * blockDim.x + threadIdx.x;
    if (i < n4) p[i] = make_float4(0.f, 0.f, 0.f, 0.f);
}

// ---------------- edge scatter: agg[row] += ew * h[col]  (lmda=1) ----------------
__global__ __launch_bounds__(256) void scatter_kernel(
    const float* __restrict__ ew,
    const float* __restrict__ H, float* __restrict__ AGG)
{
    int wid  = (blockIdx.x * blockDim.x + threadIdx.x) >> 5;
    int lane = threadIdx.x & 31;
    if (wid >= NE) return;
    int r = g_row[wid];
    int c = g_col[wid];
    float w = ew[wid];
    float4 v = *(const float4*)(H + (size_t)c * DIM + lane * 4);
    float* dst = AGG + (size_t)r * DIM + lane * 4;
    asm volatile("red.global.add.v4.f32 [%0], {%1,%2,%3,%4};"
                 :: "l"(dst), "f"(v.x * w), "f"(v.y * w), "f"(v.z * w), "f"(v.w * w)
                 : "memory");
}

// ---------------- GEMM: C[M,128] = A[M,128] @ W[128,128] + b  (optional relu) ----------------
template<bool RELU>
__global__ __launch_bounds__(256) void gemm128_kernel(
    const float* __restrict__ A, const float* __restrict__ W,
    const float* __restrict__ bias, float* __restrict__ C)
{
    __shared__ float As[64 * 32];
    __shared__ float Ws[32 * 128];
    int tid = threadIdx.x;
    int tx = tid & 31, ty = tid >> 5;     // tx: col group, ty: row group
    int m0 = blockIdx.x * 64;
    float acc[8][4] = {};
    for (int kt = 0; kt < 4; ++kt) {
        int k0 = kt * 32;
#pragma unroll
        for (int i = 0; i < 2; ++i) {                 // A tile 64x32 = 512 float4
            int f = tid * 2 + i;
            int row = f >> 3, cb = f & 7;
            int gr = m0 + row;
            float4 v = make_float4(0.f, 0.f, 0.f, 0.f);
            if (gr < NN) v = *(const float4*)(A + (size_t)gr * DIM + k0 + cb * 4);
            *(float4*)(As + row * 32 + cb * 4) = v;
        }
#pragma unroll
        for (int i = 0; i < 4; ++i) {                 // W tile 32x128 = 1024 float4
            int f = tid + 256 * i;
            int row = f >> 5, cb = f & 31;
            *(float4*)(Ws + row * 128 + cb * 4) =
                *(const float4*)(W + (size_t)(k0 + row) * DIM + cb * 4);
        }
        __syncthreads();
#pragma unroll
        for (int k = 0; k < 32; ++k) {
            float4 w = *(const float4*)(Ws + k * 128 + tx * 4);
#pragma unroll
            for (int i = 0; i < 8; ++i) {
                float a = As[(ty + 8 * i) * 32 + k];
                acc[i][0] += a * w.x; acc[i][1] += a * w.y;
                acc[i][2] += a * w.z; acc[i][3] += a * w.w;
            }
        }
        __syncthreads();
    }
    float4 bv = *(const float4*)(bias + tx * 4);
#pragma unroll
    for (int i = 0; i < 8; ++i) {
        int gr = m0 + ty + 8 * i;
        if (gr < NN) {
            float4 o;
            o.x = acc[i][0] + bv.x; o.y = acc[i][1] + bv.y;
            o.z = acc[i][2] + bv.z; o.w = acc[i][3] + bv.w;
            if (RELU) {
                o.x = fmaxf(o.x, 0.f); o.y = fmaxf(o.y, 0.f);
                o.z = fmaxf(o.z, 0.f); o.w = fmaxf(o.w, 0.f);
            }
            *(float4*)(C + (size_t)gr * DIM + tx * 4) = o;
        }
    }
}

// ---------------- fused: C = dropout(relu([agg*inv, X] @ Wagg + b)) ----------------
__global__ __launch_bounds__(256) void gemm_agg_kernel(
    const float* __restrict__ AGG, const float* X,
    const float* __restrict__ Wagg,   // [256,128]
    const float* __restrict__ bias, int layer, float* C)
{
    __shared__ float As[64 * 32];
    __shared__ float Ws[32 * 128];
    int tid = threadIdx.x;
    int tx = tid & 31, ty = tid >> 5;
    int m0 = blockIdx.x * 64;
    float acc[8][4] = {};
    for (int kt = 0; kt < 8; ++kt) {
        int k0 = kt * 32;
#pragma unroll
        for (int i = 0; i < 2; ++i) {
            int f = tid * 2 + i;
            int row = f >> 3, cb = f & 7;
            int gr = m0 + row;
            float4 v = make_float4(0.f, 0.f, 0.f, 0.f);
            if (gr < NN) {
                if (kt < 4) {
                    v = *(const float4*)(AGG + (size_t)gr * DIM + k0 + cb * 4);
                    float s = g_deg[gr];
                    v.x *= s; v.y *= s; v.z *= s; v.w *= s;
                } else {
                    v = *(const float4*)(X + (size_t)gr * DIM + (k0 - 128) + cb * 4);
                }
            }
            *(float4*)(As + row * 32 + cb * 4) = v;
        }
#pragma unroll
        for (int i = 0; i < 4; ++i) {
            int f = tid + 256 * i;
            int row = f >> 5, cb = f & 31;
            *(float4*)(Ws + row * 128 + cb * 4) =
                *(const float4*)(Wagg + (size_t)(k0 + row) * DIM + cb * 4);
        }
        __syncthreads();
#pragma unroll
        for (int k = 0; k < 32; ++k) {
            float4 w = *(const float4*)(Ws + k * 128 + tx * 4);
#pragma unroll
            for (int i = 0; i < 8; ++i) {
                float a = As[(ty + 8 * i) * 32 + k];
                acc[i][0] += a * w.x; acc[i][1] += a * w.y;
                acc[i][2] += a * w.z; acc[i][3] += a * w.w;
            }
        }
        __syncthreads();
    }
    float4 bv = *(const float4*)(bias + tx * 4);
#pragma unroll
    for (int i = 0; i < 8; ++i) {
        int gr = m0 + ty + 8 * i;
        if (gr < NN) {
            unsigned jb = (unsigned)gr * DIM + tx * 4;
            unsigned word = g_mask[layer][jb >> 5];
            unsigned sh = jb & 31;                    // tx*4 mod 32, +3 stays in word
            float4 o;
            o.x = fmaxf(acc[i][0] + bv.x, 0.f);
            o.y = fmaxf(acc[i][1] + bv.y, 0.f);
            o.z = fmaxf(acc[i][2] + bv.z, 0.f);
            o.w = fmaxf(acc[i][3] + bv.w, 0.f);
            o.x = ((word >> (sh + 0)) & 1u) ? o.x * 2.f : 0.f;
            o.y = ((word >> (sh + 1)) & 1u) ? o.y * 2.f : 0.f;
            o.z = ((word >> (sh + 2)) & 1u) ? o.z * 2.f : 0.f;
            o.w = ((word >> (sh + 3)) & 1u) ? o.w * 2.f : 0.f;
            *(float4*)(C + (size_t)gr * DIM + tx * 4) = o;
        }
    }
}

// ---------------- final tiny GEMM: y = t @ W2[128,10] + b2 ----------------
__global__ __launch_bounds__(256) void mlp2_kernel(
    const float* __restrict__ T, const float* __restrict__ W2,
    const float* __restrict__ b2, float* __restrict__ Y)
{
    __shared__ float Wt[10 * 128];   // transposed: Wt[j*128 + k]
    __shared__ float bs[10];
    int tid = threadIdx.x;
    for (int f = tid; f < 1280; f += 256) {
        int k = f / 10, j = f % 10;
        Wt[j * 128 + k] = W2[f];
    }
    if (tid < 10) bs[tid] = b2[tid];
    __syncthreads();
    int warp = tid >> 5, lane = tid & 31;
    int n = blockIdx.x * 8 + warp;
    if (n >= NN) return;
    float4 h = *(const float4*)(T + (size_t)n * 128 + lane * 4);
#pragma unroll
    for (int j = 0; j < 10; ++j) {
        float4 w = *(const float4*)(Wt + j * 128 + lane * 4);
        float s = h.x * w.x + h.y * w.y + h.z * w.z + h.w * w.w;
        s += __shfl_xor_sync(0xffffffffu, s, 16);
        s += __shfl_xor_sync(0xffffffffu, s, 8);
        s += __shfl_xor_sync(0xffffffffu, s, 4);
        s += __shfl_xor_sync(0xffffffffu, s, 2);
        s += __shfl_xor_sync(0xffffffffu, s, 1);
        if (lane == 0) Y[(size_t)n * 10 + j] = s + bs[j];
    }
}

// ---------------- launch ----------------
extern "C" void kernel_launch(void* const* d_in, const int* in_sizes, int n_in,
                              void* d_out, int out_size)
{
    const float* x        = (const float*)d_in[0];
    const void*  ei_raw   = d_in[1];
    const float* ew       = (const float*)d_in[2];
    const float* W_lin_in = (const float*)d_in[3];
    const float* b_lin_in = (const float*)d_in[4];
    const float* W_agg_in = (const float*)d_in[5];
    const float* b_agg_in = (const float*)d_in[6];
    const float* W_lin_h  = (const float*)d_in[7];
    const float* b_lin_h  = (const float*)d_in[8];
    const float* W_agg_h  = (const float*)d_in[9];
    const float* b_agg_h  = (const float*)d_in[10];
    const float* W_mlp1   = (const float*)d_in[11];
    const float* b_mlp1   = (const float*)d_in[12];
    const float* W_mlp2   = (const float*)d_in[13];
    const float* b_mlp2   = (const float*)d_in[14];
    float* out   = (float*)d_out;
    float* out_h = out;                       // [NN,128]
    float* out_y = out + (size_t)NN * 128;    // [NN,10]

    // JAX partitionable (fold-like) split: dk[i] = threefry2x32(key, (0, i)),
    // new key = full (y0, y1) output pair. key(42) = (0, 42).
    unsigned ka[3], kb[3];
    threefry2x32(0u, 42u, 0u, 0u, ka[0], kb[0]);
    threefry2x32(0u, 42u, 0u, 1u, ka[1], kb[1]);
    threefry2x32(0u, 42u, 0u, 2u, ka[2], kb[2]);

    float *p_h, *p_agg, *p_x1, *p_x2;
    cudaGetSymbolAddress((void**)&p_h,   g_h);
    cudaGetSymbolAddress((void**)&p_agg, g_agg);
    cudaGetSymbolAddress((void**)&p_x1,  g_x1);
    cudaGetSymbolAddress((void**)&p_x2,  g_x2);

    detect_kernel<<<1, 1024>>>((const unsigned*)ei_raw);
    unpack_kernel<<<(2 * NE + 255) / 256, 256>>>(ei_raw);
    zero_deg_kernel<<<(NN + 255) / 256, 256>>>();
    deg_kernel<<<(NE + 255) / 256, 256>>>();
    inv_kernel<<<(NN + 255) / 256, 256>>>();
    for (int l = 0; l < 3; ++l)
        mask_kernel<<<TOT / 256, 256>>>(ka[l], kb[l], l);

    const int GBLK = (NN + 63) / 64;
    const float* Win[3] = { W_lin_in, W_lin_h, W_lin_h };
    const float* bin[3] = { b_lin_in, b_lin_h, b_lin_h };
    const float* Wag[3] = { W_agg_in, W_agg_h, W_agg_h };
    const float* bag[3] = { b_agg_in, b_agg_h, b_agg_h };
    float* outs[3] = { p_x1, p_x2, out_h };

    const float* inp = x;
    for (int l = 0; l < 3; ++l) {
        gemm128_kernel<false><<<GBLK, 256>>>(inp, Win[l], bin[l], p_h);
        zero4_kernel<<<(TOT / 4 + 255) / 256, 256>>>((float4*)p_agg, TOT / 4);
        scatter_kernel<<<NE / 8, 256>>>(ew, p_h, p_agg);
        gemm_agg_kernel<<<GBLK, 256>>>(p_agg, inp, Wag[l], bag[l], l, outs[l]);
        inp = outs[l];
    }
    gemm128_kernel<true><<<GBLK, 256>>>(out_h, W_mlp1, b_mlp1, p_agg);
    mlp2_kernel<<<(NN + 7) / 8, 256>>>(p_agg, W_mlp2, b_mlp2, out_y);
}

// round 12
// speedup vs baseline: 1.9031x; 1.9031x over previous
#include <cuda_runtime.h>
#include <cstdint>

#define NN 50000
#define NE 800000
#define DIM 128
#define TOT (NN * DIM)            // 6,400,000
#define MASK_WORDS (TOT / 32)     // 200,000
#define SCAN_BLK 1024
#define NBLKS ((NN + SCAN_BLK - 1) / SCAN_BLK)   // 49

// ---------------- scratch (no allocation allowed) ----------------
__device__ float g_h[TOT];        // lin(x) output per layer
__device__ float g_agg[TOT];      // aggregated messages / mlp1 scratch
__device__ float g_x1[TOT];       // layer-1 output
__device__ float g_x2[TOT];       // layer-2 output
__device__ float g_inv[NN];       // 1/max(deg,1)
__device__ unsigned g_mask[3][MASK_WORDS];
__device__ int g_row[NE];
__device__ int g_col[NE];
__device__ int g_is64;
// CSR
__device__ int g_cnt[NN];
__device__ int g_off[NN + 1];
__device__ int g_cur[NN];
__device__ int g_bsum[64];
__device__ int g_dcol[NE];
__device__ float g_dw[NE];

// ---------------- threefry2x32 (exact JAX semantics) ----------------
__host__ __device__ __forceinline__ void threefry2x32(
    unsigned k0, unsigned k1, unsigned x0, unsigned x1,
    unsigned& y0, unsigned& y1)
{
    unsigned ks0 = k0, ks1 = k1, ks2 = k0 ^ k1 ^ 0x1BD11BDAu;
#define TF_R(r) { x0 += x1; x1 = (x1 << (r)) | (x1 >> (32 - (r))); x1 ^= x0; }
    x0 += ks0; x1 += ks1;
    TF_R(13) TF_R(15) TF_R(26) TF_R(6)
    x0 += ks1; x1 += ks2 + 1u;
    TF_R(17) TF_R(29) TF_R(16) TF_R(24)
    x0 += ks2; x1 += ks0 + 2u;
    TF_R(13) TF_R(15) TF_R(26) TF_R(6)
    x0 += ks0; x1 += ks1 + 3u;
    TF_R(17) TF_R(29) TF_R(16) TF_R(24)
    x0 += ks1; x1 += ks2 + 4u;
    TF_R(13) TF_R(15) TF_R(26) TF_R(6)
    y0 = x0 + ks2; y1 = x1 + ks0 + 5u;
#undef TF_R
}

// ---------------- edge-index dtype detect + unpack ----------------
__global__ void detect_kernel(const unsigned* __restrict__ raw)
{
    __shared__ int any;
    if (threadIdx.x == 0) any = 0;
    __syncthreads();
    unsigned w = raw[threadIdx.x * 2 + 1];
    if (w != 0u) atomicOr(&any, 1);
    __syncthreads();
    if (threadIdx.x == 0) g_is64 = (any == 0) ? 1 : 0;
}
__global__ void unpack_kernel(const void* __restrict__ raw)
{
    int e = blockIdx.x * blockDim.x + threadIdx.x;
    if (e >= 2 * NE) return;
    int v;
    if (g_is64) v = (int)((const long long*)raw)[e];
    else        v = ((const int*)raw)[e];
    if (e < NE) g_row[e] = v;
    else        g_col[e - NE] = v;
}

// ---------------- dropout masks (JAX partitionable threefry) ----------------
__global__ void mask_kernel(unsigned ka, unsigned kb, int layer)
{
    unsigned j = blockIdx.x * blockDim.x + threadIdx.x;
    unsigned y0, y1;
    threefry2x32(ka, kb, 0u, j, y0, y1);
    unsigned keep = ((y0 ^ y1) >> 31) ^ 1u;
    unsigned w = __ballot_sync(0xffffffffu, keep);
    if ((threadIdx.x & 31) == 0) g_mask[layer][j >> 5] = w;
}

// ---------------- CSR build ----------------
__global__ void zero_cnt_kernel()
{
    int i = blockIdx.x * blockDim.x + threadIdx.x;
    if (i < NN) g_cnt[i] = 0;
}
__global__ void count_kernel()
{
    int e = blockIdx.x * blockDim.x + threadIdx.x;
    if (e < NE) atomicAdd(&g_cnt[g_row[e]], 1);
}
__global__ void scan1_kernel()
{
    __shared__ int sh[SCAN_BLK];
    int i = blockIdx.x * SCAN_BLK + threadIdx.x;
    int v = (i < NN) ? g_cnt[i] : 0;
    sh[threadIdx.x] = v;
    __syncthreads();
    for (int off = 1; off < SCAN_BLK; off <<= 1) {
        int t = (threadIdx.x >= off) ? sh[threadIdx.x - off] : 0;
        __syncthreads();
        sh[threadIdx.x] += t;
        __syncthreads();
    }
    if (i < NN) g_off[i] = sh[threadIdx.x] - v;   // exclusive
    if (threadIdx.x == SCAN_BLK - 1) g_bsum[blockIdx.x] = sh[threadIdx.x];
}
__global__ void scan2_kernel()
{
    __shared__ int sh[64];
    int v = (threadIdx.x < NBLKS) ? g_bsum[threadIdx.x] : 0;
    sh[threadIdx.x] = v;
    __syncthreads();
    for (int off = 1; off < 64; off <<= 1) {
        int t = (threadIdx.x >= off) ? sh[threadIdx.x - off] : 0;
        __syncthreads();
        sh[threadIdx.x] += t;
        __syncthreads();
    }
    if (threadIdx.x < NBLKS) g_bsum[threadIdx.x] = sh[threadIdx.x] - v;
}
__global__ void scan3_kernel()
{
    int i = blockIdx.x * blockDim.x + threadIdx.x;
    if (i < NN) {
        int o = g_off[i] + g_bsum[i / SCAN_BLK];
        g_off[i] = o;
        g_cur[i] = o;
        g_inv[i] = 1.0f / (float)max(g_cnt[i], 1);
    }
    if (i == 0) g_off[NN] = NE;
}
__global__ void fill_kernel(const float* __restrict__ ew)
{
    int e = blockIdx.x * blockDim.x + threadIdx.x;
    if (e >= NE) return;
    int r = g_row[e];
    int pos = atomicAdd(&g_cur[r], 1);
    g_dcol[pos] = g_col[e];
    g_dw[pos] = ew[e];
}

// ---------------- CSR aggregation: AGG[n] = inv[n] * sum_e w_e * H[col_e] ----------------
__global__ __launch_bounds__(256) void aggregate_kernel(
    const float* __restrict__ H, float* __restrict__ AGG)
{
    int wid  = (blockIdx.x * blockDim.x + threadIdx.x) >> 5;
    int lane = threadIdx.x & 31;
    if (wid >= NN) return;
    int beg = g_off[wid], end = g_off[wid + 1];
    float4 a0 = make_float4(0.f, 0.f, 0.f, 0.f);
    float4 a1 = make_float4(0.f, 0.f, 0.f, 0.f);
    int e = beg;
    for (; e + 1 < end; e += 2) {
        int c0 = g_dcol[e], c1 = g_dcol[e + 1];
        float w0 = g_dw[e], w1 = g_dw[e + 1];
        float4 v0 = *(const float4*)(H + (size_t)c0 * DIM + lane * 4);
        float4 v1 = *(const float4*)(H + (size_t)c1 * DIM + lane * 4);
        a0.x += w0 * v0.x; a0.y += w0 * v0.y; a0.z += w0 * v0.z; a0.w += w0 * v0.w;
        a1.x += w1 * v1.x; a1.y += w1 * v1.y; a1.z += w1 * v1.z; a1.w += w1 * v1.w;
    }
    if (e < end) {
        int c0 = g_dcol[e];
        float w0 = g_dw[e];
        float4 v0 = *(const float4*)(H + (size_t)c0 * DIM + lane * 4);
        a0.x += w0 * v0.x; a0.y += w0 * v0.y; a0.z += w0 * v0.z; a0.w += w0 * v0.w;
    }
    float s = g_inv[wid];
    float4 o;
    o.x = (a0.x + a1.x) * s; o.y = (a0.y + a1.y) * s;
    o.z = (a0.z + a1.z) * s; o.w = (a0.w + a1.w) * s;
    *(float4*)(AGG + (size_t)wid * DIM + lane * 4) = o;
}

// ---------------- 3xTF32 tensor-core GEMM ----------------
__device__ __forceinline__ unsigned f2tf(float x)
{
    unsigned r;
    asm("cvt.rna.tf32.f32 %0, %1;" : "=r"(r) : "f"(x));
    return r;
}
__device__ __forceinline__ void mma_tf32(float* d, const unsigned* a, const unsigned* b)
{
    asm volatile(
        "mma.sync.aligned.m16n8k8.row.col.f32.tf32.tf32.f32 "
        "{%0,%1,%2,%3}, {%4,%5,%6,%7}, {%8,%9}, {%0,%1,%2,%3};"
        : "+f"(d[0]), "+f"(d[1]), "+f"(d[2]), "+f"(d[3])
        : "r"(a[0]), "r"(a[1]), "r"(a[2]), "r"(a[3]), "r"(b[0]), "r"(b[1]));
}

// C[M,128] = concat_or_plain(A,A2)[M, K] @ W[K,128] + bias, then opt relu/dropout.
// KTILES*16 = K. Block: 128 rows x 128 cols, 256 threads (8 warps, 4M x 2N).
template<int KTILES, bool CONCAT, bool RELU, bool DROP>
__global__ __launch_bounds__(256, 2) void tgemm_kernel(
    const float* __restrict__ A, const float* __restrict__ A2,
    const float* __restrict__ W, const float* __restrict__ bias,
    const unsigned* __restrict__ mask, float* __restrict__ C)
{
    __shared__ float As_h[128 * 20];
    __shared__ float As_l[128 * 20];
    __shared__ float Ws_h[16 * 136];
    __shared__ float Ws_l[16 * 136];
    __shared__ float bs[128];

    int tid = threadIdx.x;
    int lane = tid & 31, warp = tid >> 5;
    int wm = warp & 3, wn = warp >> 2;        // 4 x 2 warp grid
    int m0 = blockIdx.x * 128;
    int lr = lane >> 2, lc = lane & 3;        // groupID / threadID-in-group

    if (tid < 32) *(float4*)(bs + tid * 4) = *(const float4*)(bias + tid * 4);

    float acc[2][8][4];
#pragma unroll
    for (int i = 0; i < 2; ++i)
#pragma unroll
        for (int j = 0; j < 8; ++j)
#pragma unroll
            for (int k = 0; k < 4; ++k) acc[i][j][k] = 0.f;

    for (int kt = 0; kt < KTILES; ++kt) {
        int k0 = kt * 16;
        const float* Asrc = A;
        int kbase = k0;
        if (CONCAT && k0 >= 128) { Asrc = A2; kbase = k0 - 128; }
        __syncthreads();
        // A tile: 128x16 -> hi/lo, stride 20
#pragma unroll
        for (int i = 0; i < 2; ++i) {
            int f = tid * 2 + i;
            int row = f >> 2, cb = f & 3;
            int gr = m0 + row;
            float4 v = make_float4(0.f, 0.f, 0.f, 0.f);
            if (gr < NN) v = *(const float4*)(Asrc + (size_t)gr * DIM + kbase + cb * 4);
            float hx = __uint_as_float(f2tf(v.x)), hy = __uint_as_float(f2tf(v.y));
            float hz = __uint_as_float(f2tf(v.z)), hw = __uint_as_float(f2tf(v.w));
            float* ph = As_h + row * 20 + cb * 4;
            float* pl = As_l + row * 20 + cb * 4;
            ph[0] = hx; ph[1] = hy; ph[2] = hz; ph[3] = hw;
            pl[0] = v.x - hx; pl[1] = v.y - hy; pl[2] = v.z - hz; pl[3] = v.w - hw;
        }
        // W tile: 16x128 -> hi/lo, stride 136
#pragma unroll
        for (int i = 0; i < 2; ++i) {
            int f = tid * 2 + i;
            int r = f >> 5, cb = f & 31;
            float4 v = *(const float4*)(W + (size_t)(k0 + r) * DIM + cb * 4);
            float hx = __uint_as_float(f2tf(v.x)), hy = __uint_as_float(f2tf(v.y));
            float hz = __uint_as_float(f2tf(v.z)), hw = __uint_as_float(f2tf(v.w));
            float* ph = Ws_h + r * 136 + cb * 4;
            float* pl = Ws_l + r * 136 + cb * 4;
            ph[0] = hx; ph[1] = hy; ph[2] = hz; ph[3] = hw;
            pl[0] = v.x - hx; pl[1] = v.y - hy; pl[2] = v.z - hz; pl[3] = v.w - hw;
        }
        __syncthreads();
#pragma unroll
        for (int q = 0; q < 16; q += 8) {
            unsigned ah[2][4], al[2][4];
#pragma unroll
            for (int mt = 0; mt < 2; ++mt) {
                int rb = wm * 32 + mt * 16 + lr;
                int kk = q + lc;
                ah[mt][0] = __float_as_uint(As_h[rb * 20 + kk]);
                ah[mt][1] = __float_as_uint(As_h[(rb + 8) * 20 + kk]);
                ah[mt][2] = __float_as_uint(As_h[rb * 20 + kk + 4]);
                ah[mt][3] = __float_as_uint(As_h[(rb + 8) * 20 + kk + 4]);
                al[mt][0] = __float_as_uint(As_l[rb * 20 + kk]);
                al[mt][1] = __float_as_uint(As_l[(rb + 8) * 20 + kk]);
                al[mt][2] = __float_as_uint(As_l[rb * 20 + kk + 4]);
                al[mt][3] = __float_as_uint(As_l[(rb + 8) * 20 + kk + 4]);
            }
#pragma unroll
            for (int nt = 0; nt < 8; ++nt) {
                int cb2 = wn * 64 + nt * 8 + lr;
                int kk = q + lc;
                unsigned bh[2], bl[2];
                bh[0] = __float_as_uint(Ws_h[kk * 136 + cb2]);
                bh[1] = __float_as_uint(Ws_h[(kk + 4) * 136 + cb2]);
                bl[0] = __float_as_uint(Ws_l[kk * 136 + cb2]);
                bl[1] = __float_as_uint(Ws_l[(kk + 4) * 136 + cb2]);
#pragma unroll
                for (int mt = 0; mt < 2; ++mt) {
                    mma_tf32(acc[mt][nt], ah[mt], bh);
                    mma_tf32(acc[mt][nt], ah[mt], bl);
                    mma_tf32(acc[mt][nt], al[mt], bh);
                }
            }
        }
    }
    // epilogue
#pragma unroll
    for (int mt = 0; mt < 2; ++mt) {
#pragma unroll
        for (int nt = 0; nt < 8; ++nt) {
            int row0 = m0 + wm * 32 + mt * 16 + lr;
            int col = wn * 64 + nt * 8 + lc * 2;
#pragma unroll
            for (int h = 0; h < 2; ++h) {
                int row = row0 + h * 8;
                if (row < NN) {
                    float v0 = acc[mt][nt][h * 2 + 0] + bs[col];
                    float v1 = acc[mt][nt][h * 2 + 1] + bs[col + 1];
                    if (RELU || DROP) { v0 = fmaxf(v0, 0.f); v1 = fmaxf(v1, 0.f); }
                    if (DROP) {
                        unsigned word = mask[row * 4 + (col >> 5)];
                        unsigned sh = col & 31;
                        v0 = ((word >> sh) & 1u) ? v0 * 2.f : 0.f;
                        v1 = ((word >> (sh + 1)) & 1u) ? v1 * 2.f : 0.f;
                    }
                    float2 o = make_float2(v0, v1);
                    *(float2*)(C + (size_t)row * DIM + col) = o;
                }
            }
        }
    }
}

// ---------------- final tiny GEMM: y = t @ W2[128,10] + b2 ----------------
__global__ __launch_bounds__(256) void mlp2_kernel(
    const float* __restrict__ T, const float* __restrict__ W2,
    const float* __restrict__ b2, float* __restrict__ Y)
{
    __shared__ float Wt[10 * 128];
    __shared__ float bsm[10];
    int tid = threadIdx.x;
    for (int f = tid; f < 1280; f += 256) {
        int k = f / 10, j = f % 10;
        Wt[j * 128 + k] = W2[f];
    }
    if (tid < 10) bsm[tid] = b2[tid];
    __syncthreads();
    int warp = tid >> 5, lane = tid & 31;
    int n = blockIdx.x * 8 + warp;
    if (n >= NN) return;
    float4 h = *(const float4*)(T + (size_t)n * 128 + lane * 4);
#pragma unroll
    for (int j = 0; j < 10; ++j) {
        float4 w = *(const float4*)(Wt + j * 128 + lane * 4);
        float s = h.x * w.x + h.y * w.y + h.z * w.z + h.w * w.w;
        s += __shfl_xor_sync(0xffffffffu, s, 16);
        s += __shfl_xor_sync(0xffffffffu, s, 8);
        s += __shfl_xor_sync(0xffffffffu, s, 4);
        s += __shfl_xor_sync(0xffffffffu, s, 2);
        s += __shfl_xor_sync(0xffffffffu, s, 1);
        if (lane == 0) Y[(size_t)n * 10 + j] = s + bsm[j];
    }
}

// ---------------- launch ----------------
extern "C" void kernel_launch(void* const* d_in, const int* in_sizes, int n_in,
                              void* d_out, int out_size)
{
    const float* x        = (const float*)d_in[0];
    const void*  ei_raw   = d_in[1];
    const float* ew       = (const float*)d_in[2];
    const float* W_lin_in = (const float*)d_in[3];
    const float* b_lin_in = (const float*)d_in[4];
    const float* W_agg_in = (const float*)d_in[5];
    const float* b_agg_in = (const float*)d_in[6];
    const float* W_lin_h  = (const float*)d_in[7];
    const float* b_lin_h  = (const float*)d_in[8];
    const float* W_agg_h  = (const float*)d_in[9];
    const float* b_agg_h  = (const float*)d_in[10];
    const float* W_mlp1   = (const float*)d_in[11];
    const float* b_mlp1   = (const float*)d_in[12];
    const float* W_mlp2   = (const float*)d_in[13];
    const float* b_mlp2   = (const float*)d_in[14];
    float* out   = (float*)d_out;
    float* out_h = out;                       // [NN,128]
    float* out_y = out + (size_t)NN * 128;    // [NN,10]

    // JAX partitionable split: dk[i] = threefry2x32(key=(0,42), (0, i))
    unsigned ka[3], kb[3];
    threefry2x32(0u, 42u, 0u, 0u, ka[0], kb[0]);
    threefry2x32(0u, 42u, 0u, 1u, ka[1], kb[1]);
    threefry2x32(0u, 42u, 0u, 2u, ka[2], kb[2]);

    float *p_h, *p_agg, *p_x1, *p_x2;
    unsigned* p_mask;
    cudaGetSymbolAddress((void**)&p_h,    g_h);
    cudaGetSymbolAddress((void**)&p_agg,  g_agg);
    cudaGetSymbolAddress((void**)&p_x1,   g_x1);
    cudaGetSymbolAddress((void**)&p_x2,   g_x2);
    cudaGetSymbolAddress((void**)&p_mask, g_mask);

    detect_kernel<<<1, 1024>>>((const unsigned*)ei_raw);
    unpack_kernel<<<(2 * NE + 255) / 256, 256>>>(ei_raw);
    zero_cnt_kernel<<<(NN + 255) / 256, 256>>>();
    count_kernel<<<(NE + 255) / 256, 256>>>();
    scan1_kernel<<<NBLKS, SCAN_BLK>>>();
    scan2_kernel<<<1, 64>>>();
    scan3_kernel<<<(NN + 255) / 256, 256>>>();
    fill_kernel<<<(NE + 255) / 256, 256>>>(ew);
    for (int l = 0; l < 3; ++l)
        mask_kernel<<<TOT / 256, 256>>>(ka[l], kb[l], l);

    const int GBLK = (NN + 127) / 128;   // 391
    const float* Win[3] = { W_lin_in, W_lin_h, W_lin_h };
    const float* bin[3] = { b_lin_in, b_lin_h, b_lin_h };
    const float* Wag[3] = { W_agg_in, W_agg_h, W_agg_h };
    const float* bag[3] = { b_agg_in, b_agg_h, b_agg_h };
    float* outs[3] = { p_x1, p_x2, out_h };

    const float* inp = x;
    for (int l = 0; l < 3; ++l) {
        tgemm_kernel<8, false, false, false><<<GBLK, 256>>>(
            inp, nullptr, Win[l], bin[l], nullptr, p_h);
        aggregate_kernel<<<(NN + 7) / 8, 256>>>(p_h, p_agg);
        tgemm_kernel<16, true, true, true><<<GBLK, 256>>>(
            p_agg, inp, Wag[l], bag[l], p_mask + (size_t)l * MASK_WORDS, outs[l]);
        inp = outs[l];
    }
    tgemm_kernel<8, false, true, false><<<GBLK, 256>>>(
        out_h, nullptr, W_mlp1, b_mlp1, nullptr, p_agg);
    mlp2_kernel<<<(NN + 7) / 8, 256>>>(p_agg, W_mlp2, b_mlp2, out_y);
}

// round 16
// speedup vs baseline: 2.1861x; 1.1487x over previous
#include <cuda_runtime.h>
#include <cstdint>

#define NN 50000
#define NE 800000
#define DIM 128
#define TOT (NN * DIM)            // 6,400,000
#define MASK_WORDS (TOT / 32)     // 200,000
#define SCAN_BLK 1024
#define NBLKS ((NN + SCAN_BLK - 1) / SCAN_BLK)   // 49

// ---------------- scratch (no allocation allowed) ----------------
__device__ float g_h[TOT];
__device__ float g_agg[TOT];
__device__ float g_x1[TOT];
__device__ float g_x2[TOT];
__device__ float g_inv[NN];
__device__ unsigned g_mask[3][MASK_WORDS];
__device__ int g_row[NE];
__device__ int g_col[NE];
__device__ int g_is64;
// CSR
__device__ int g_cnt[NN];
__device__ int g_off[NN + 1];
__device__ int g_cur[NN];
__device__ int g_bsum[64];
__device__ int g_dcol[NE];
__device__ float g_dw[NE];

// ---------------- threefry2x32 (exact JAX semantics) ----------------
__host__ __device__ __forceinline__ void threefry2x32(
    unsigned k0, unsigned k1, unsigned x0, unsigned x1,
    unsigned& y0, unsigned& y1)
{
    unsigned ks0 = k0, ks1 = k1, ks2 = k0 ^ k1 ^ 0x1BD11BDAu;
#define TF_R(r) { x0 += x1; x1 = (x1 << (r)) | (x1 >> (32 - (r))); x1 ^= x0; }
    x0 += ks0; x1 += ks1;
    TF_R(13) TF_R(15) TF_R(26) TF_R(6)
    x0 += ks1; x1 += ks2 + 1u;
    TF_R(17) TF_R(29) TF_R(16) TF_R(24)
    x0 += ks2; x1 += ks0 + 2u;
    TF_R(13) TF_R(15) TF_R(26) TF_R(6)
    x0 += ks0; x1 += ks1 + 3u;
    TF_R(17) TF_R(29) TF_R(16) TF_R(24)
    x0 += ks1; x1 += ks2 + 4u;
    TF_R(13) TF_R(15) TF_R(26) TF_R(6)
    y0 = x0 + ks2; y1 = x1 + ks0 + 5u;
#undef TF_R
}

// ---------------- edge-index dtype detect + unpack (+degree count) ----------------
__global__ void detect_kernel(const unsigned* __restrict__ raw)
{
    __shared__ int any;
    if (threadIdx.x == 0) any = 0;
    __syncthreads();
    unsigned w = raw[threadIdx.x * 2 + 1];
    if (w != 0u) atomicOr(&any, 1);
    __syncthreads();
    if (threadIdx.x == 0) g_is64 = (any == 0) ? 1 : 0;
}
__global__ void zero_cnt_kernel()
{
    int i = blockIdx.x * blockDim.x + threadIdx.x;
    if (i < NN) g_cnt[i] = 0;
}
__global__ void unpack_count_kernel(const void* __restrict__ raw)
{
    int e = blockIdx.x * blockDim.x + threadIdx.x;
    if (e >= 2 * NE) return;
    int v;
    if (g_is64) v = (int)((const long long*)raw)[e];
    else        v = ((const int*)raw)[e];
    if (e < NE) { g_row[e] = v; atomicAdd(&g_cnt[v], 1); }
    else          g_col[e - NE] = v;
}

// ---------------- dropout masks (JAX partitionable threefry) ----------------
__global__ void mask_kernel(unsigned ka, unsigned kb, int layer)
{
    unsigned j = blockIdx.x * blockDim.x + threadIdx.x;
    unsigned y0, y1;
    threefry2x32(ka, kb, 0u, j, y0, y1);
    unsigned keep = ((y0 ^ y1) >> 31) ^ 1u;
    unsigned w = __ballot_sync(0xffffffffu, keep);
    if ((threadIdx.x & 31) == 0) g_mask[layer][j >> 5] = w;
}

// ---------------- CSR build ----------------
__global__ void scan1_kernel()
{
    __shared__ int sh[SCAN_BLK];
    int i = blockIdx.x * SCAN_BLK + threadIdx.x;
    int v = (i < NN) ? g_cnt[i] : 0;
    sh[threadIdx.x] = v;
    __syncthreads();
    for (int off = 1; off < SCAN_BLK; off <<= 1) {
        int t = (threadIdx.x >= off) ? sh[threadIdx.x - off] : 0;
        __syncthreads();
        sh[threadIdx.x] += t;
        __syncthreads();
    }
    if (i < NN) g_off[i] = sh[threadIdx.x] - v;   // exclusive
    if (threadIdx.x == SCAN_BLK - 1) g_bsum[blockIdx.x] = sh[threadIdx.x];
}
__global__ void scan2_kernel()
{
    __shared__ int sh[64];
    int v = (threadIdx.x < NBLKS) ? g_bsum[threadIdx.x] : 0;
    sh[threadIdx.x] = v;
    __syncthreads();
    for (int off = 1; off < 64; off <<= 1) {
        int t = (threadIdx.x >= off) ? sh[threadIdx.x - off] : 0;
        __syncthreads();
        sh[threadIdx.x] += t;
        __syncthreads();
    }
    if (threadIdx.x < NBLKS) g_bsum[threadIdx.x] = sh[threadIdx.x] - v;
}
__global__ void scan3_kernel()
{
    int i = blockIdx.x * blockDim.x + threadIdx.x;
    if (i < NN) {
        int o = g_off[i] + g_bsum[i / SCAN_BLK];
        g_off[i] = o;
        g_cur[i] = o;
        g_inv[i] = 1.0f / (float)max(g_cnt[i], 1);
    }
    if (i == 0) g_off[NN] = NE;
}
__global__ void fill_kernel(const float* __restrict__ ew)
{
    int e = blockIdx.x * blockDim.x + threadIdx.x;
    if (e >= NE) return;
    int r = g_row[e];
    int pos = atomicAdd(&g_cur[r], 1);
    g_dcol[pos] = g_col[e];
    g_dw[pos] = ew[e];
}

// ---------------- CSR aggregation: AGG[n] = inv[n] * sum_e w_e * H[col_e] ----------------
__global__ __launch_bounds__(256) void aggregate_kernel(
    const float* __restrict__ H, float* __restrict__ AGG)
{
    int wid  = (blockIdx.x * blockDim.x + threadIdx.x) >> 5;
    int lane = threadIdx.x & 31;
    if (wid >= NN) return;
    int beg = g_off[wid], end = g_off[wid + 1];
    float4 a0 = make_float4(0.f, 0.f, 0.f, 0.f);
    float4 a1 = make_float4(0.f, 0.f, 0.f, 0.f);
    int e = beg;
    for (; e + 1 < end; e += 2) {
        int c0 = g_dcol[e], c1 = g_dcol[e + 1];
        float w0 = g_dw[e], w1 = g_dw[e + 1];
        float4 v0 = *(const float4*)(H + (size_t)c0 * DIM + lane * 4);
        float4 v1 = *(const float4*)(H + (size_t)c1 * DIM + lane * 4);
        a0.x += w0 * v0.x; a0.y += w0 * v0.y; a0.z += w0 * v0.z; a0.w += w0 * v0.w;
        a1.x += w1 * v1.x; a1.y += w1 * v1.y; a1.z += w1 * v1.z; a1.w += w1 * v1.w;
    }
    if (e < end) {
        int c0 = g_dcol[e];
        float w0 = g_dw[e];
        float4 v0 = *(const float4*)(H + (size_t)c0 * DIM + lane * 4);
        a0.x += w0 * v0.x; a0.y += w0 * v0.y; a0.z += w0 * v0.z; a0.w += w0 * v0.w;
    }
    float s = g_inv[wid];
    float4 o;
    o.x = (a0.x + a1.x) * s; o.y = (a0.y + a1.y) * s;
    o.z = (a0.z + a1.z) * s; o.w = (a0.w + a1.w) * s;
    *(float4*)(AGG + (size_t)wid * DIM + lane * 4) = o;
}

// ---------------- 3xTF32 tensor-core GEMM (software-pipelined) ----------------
__device__ __forceinline__ unsigned f2tf(float x)
{
    unsigned r;
    asm("cvt.rna.tf32.f32 %0, %1;" : "=r"(r) : "f"(x));
    return r;
}
__device__ __forceinline__ void mma_tf32(float* d, const unsigned* a, const unsigned* b)
{
    asm volatile(
        "mma.sync.aligned.m16n8k8.row.col.f32.tf32.tf32.f32 "
        "{%0,%1,%2,%3}, {%4,%5,%6,%7}, {%8,%9}, {%0,%1,%2,%3};"
        : "+f"(d[0]), "+f"(d[1]), "+f"(d[2]), "+f"(d[3])
        : "r"(a[0]), "r"(a[1]), "r"(a[2]), "r"(a[3]), "r"(b[0]), "r"(b[1]));
}

// C[M,128] = concat_or_plain(A,A2)[M,K] @ W[K,128] + bias, opt relu/dropout.
// Register-prefetch pipeline: tile kt+1 loads overlap tile kt mma.
template<int KTILES, bool CONCAT, bool RELU, bool DROP>
__global__ __launch_bounds__(256, 2) void tgemm_kernel(
    const float* __restrict__ A, const float* __restrict__ A2,
    const float* __restrict__ W, const float* __restrict__ bias,
    const unsigned* __restrict__ mask, float* __restrict__ C)
{
    __shared__ float As_h[128 * 20];
    __shared__ float As_l[128 * 20];
    __shared__ float Ws_h[16 * 136];
    __shared__ float Ws_l[16 * 136];
    __shared__ float bs[128];

    int tid = threadIdx.x;
    int lane = tid & 31, warp = tid >> 5;
    int wm = warp & 3, wn = warp >> 2;
    int m0 = blockIdx.x * 128;
    int lr = lane >> 2, lc = lane & 3;

    // per-thread fixed load coordinates
    int fa0 = tid * 2, fa1 = tid * 2 + 1;
    int arow0 = fa0 >> 2, acb0 = fa0 & 3;
    int arow1 = fa1 >> 2, acb1 = fa1 & 3;
    int wr0 = fa0 >> 5, wcb0 = fa0 & 31;
    int wr1 = fa1 >> 5, wcb1 = fa1 & 31;

    if (tid < 32) *(float4*)(bs + tid * 4) = *(const float4*)(bias + tid * 4);

    float acc[2][8][4];
#pragma unroll
    for (int i = 0; i < 2; ++i)
#pragma unroll
        for (int j = 0; j < 8; ++j)
#pragma unroll
            for (int k = 0; k < 4; ++k) acc[i][j][k] = 0.f;

    auto load_tiles = [&](int kt, float4* va, float4* vw) {
        int k0 = kt * 16;
        const float* Asrc = A;
        int kbase = k0;
        if (CONCAT && k0 >= 128) { Asrc = A2; kbase = k0 - 128; }
        int gr0 = m0 + arow0, gr1 = m0 + arow1;
        va[0] = make_float4(0.f, 0.f, 0.f, 0.f);
        va[1] = make_float4(0.f, 0.f, 0.f, 0.f);
        if (gr0 < NN) va[0] = *(const float4*)(Asrc + (size_t)gr0 * DIM + kbase + acb0 * 4);
        if (gr1 < NN) va[1] = *(const float4*)(Asrc + (size_t)gr1 * DIM + kbase + acb1 * 4);
        vw[0] = *(const float4*)(W + (size_t)(k0 + wr0) * DIM + wcb0 * 4);
        vw[1] = *(const float4*)(W + (size_t)(k0 + wr1) * DIM + wcb1 * 4);
    };

    float4 va[2], vw[2];
    load_tiles(0, va, vw);

    for (int kt = 0; kt < KTILES; ++kt) {
        __syncthreads();   // previous mma done with smem
        // convert + store current tile
        {
            float4 v = va[0];
            float hx = __uint_as_float(f2tf(v.x)), hy = __uint_as_float(f2tf(v.y));
            float hz = __uint_as_float(f2tf(v.z)), hw = __uint_as_float(f2tf(v.w));
            float* ph = As_h + arow0 * 20 + acb0 * 4;
            float* pl = As_l + arow0 * 20 + acb0 * 4;
            ph[0] = hx; ph[1] = hy; ph[2] = hz; ph[3] = hw;
            pl[0] = v.x - hx; pl[1] = v.y - hy; pl[2] = v.z - hz; pl[3] = v.w - hw;
            v = va[1];
            hx = __uint_as_float(f2tf(v.x)); hy = __uint_as_float(f2tf(v.y));
            hz = __uint_as_float(f2tf(v.z)); hw = __uint_as_float(f2tf(v.w));
            ph = As_h + arow1 * 20 + acb1 * 4;
            pl = As_l + arow1 * 20 + acb1 * 4;
            ph[0] = hx; ph[1] = hy; ph[2] = hz; ph[3] = hw;
            pl[0] = v.x - hx; pl[1] = v.y - hy; pl[2] = v.z - hz; pl[3] = v.w - hw;
            v = vw[0];
            hx = __uint_as_float(f2tf(v.x)); hy = __uint_as_float(f2tf(v.y));
            hz = __uint_as_float(f2tf(v.z)); hw = __uint_as_float(f2tf(v.w));
            ph = Ws_h + wr0 * 136 + wcb0 * 4;
            pl = Ws_l + wr0 * 136 + wcb0 * 4;
            ph[0] = hx; ph[1] = hy; ph[2] = hz; ph[3] = hw;
            pl[0] = v.x - hx; pl[1] = v.y - hy; pl[2] = v.z - hz; pl[3] = v.w - hw;
            v = vw[1];
            hx = __uint_as_float(f2tf(v.x)); hy = __uint_as_float(f2tf(v.y));
            hz = __uint_as_float(f2tf(v.z)); hw = __uint_as_float(f2tf(v.w));
            ph = Ws_h + wr1 * 136 + wcb1 * 4;
            pl = Ws_l + wr1 * 136 + wcb1 * 4;
            ph[0] = hx; ph[1] = hy; ph[2] = hz; ph[3] = hw;
            pl[0] = v.x - hx; pl[1] = v.y - hy; pl[2] = v.z - hz; pl[3] = v.w - hw;
        }
        // issue next tile's loads (latency overlaps the mma below)
        float4 na[2], nw[2];
        if (kt + 1 < KTILES) load_tiles(kt + 1, na, nw);
        __syncthreads();
#pragma unroll
        for (int q = 0; q < 16; q += 8) {
            unsigned ah[2][4], al[2][4];
#pragma unroll
            for (int mt = 0; mt < 2; ++mt) {
                int rb = wm * 32 + mt * 16 + lr;
                int kk = q + lc;
                ah[mt][0] = __float_as_uint(As_h[rb * 20 + kk]);
                ah[mt][1] = __float_as_uint(As_h[(rb + 8) * 20 + kk]);
                ah[mt][2] = __float_as_uint(As_h[rb * 20 + kk + 4]);
                ah[mt][3] = __float_as_uint(As_h[(rb + 8) * 20 + kk + 4]);
                al[mt][0] = __float_as_uint(As_l[rb * 20 + kk]);
                al[mt][1] = __float_as_uint(As_l[(rb + 8) * 20 + kk]);
                al[mt][2] = __float_as_uint(As_l[rb * 20 + kk + 4]);
                al[mt][3] = __float_as_uint(As_l[(rb + 8) * 20 + kk + 4]);
            }
#pragma unroll
            for (int nt = 0; nt < 8; ++nt) {
                int cb2 = wn * 64 + nt * 8 + lr;
                int kk = q + lc;
                unsigned bh[2], bl[2];
                bh[0] = __float_as_uint(Ws_h[kk * 136 + cb2]);
                bh[1] = __float_as_uint(Ws_h[(kk + 4) * 136 + cb2]);
                bl[0] = __float_as_uint(Ws_l[kk * 136 + cb2]);
                bl[1] = __float_as_uint(Ws_l[(kk + 4) * 136 + cb2]);
#pragma unroll
                for (int mt = 0; mt < 2; ++mt) {
                    mma_tf32(acc[mt][nt], ah[mt], bh);
                    mma_tf32(acc[mt][nt], ah[mt], bl);
                    mma_tf32(acc[mt][nt], al[mt], bh);
                }
            }
        }
        va[0] = na[0]; va[1] = na[1];
        vw[0] = nw[0]; vw[1] = nw[1];
    }
    // epilogue
#pragma unroll
    for (int mt = 0; mt < 2; ++mt) {
#pragma unroll
        for (int nt = 0; nt < 8; ++nt) {
            int row0 = m0 + wm * 32 + mt * 16 + lr;
            int col = wn * 64 + nt * 8 + lc * 2;
#pragma unroll
            for (int h = 0; h < 2; ++h) {
                int row = row0 + h * 8;
                if (row < NN) {
                    float v0 = acc[mt][nt][h * 2 + 0] + bs[col];
                    float v1 = acc[mt][nt][h * 2 + 1] + bs[col + 1];
                    if (RELU || DROP) { v0 = fmaxf(v0, 0.f); v1 = fmaxf(v1, 0.f); }
                    if (DROP) {
                        unsigned word = mask[row * 4 + (col >> 5)];
                        unsigned sh = col & 31;
                        v0 = ((word >> sh) & 1u) ? v0 * 2.f : 0.f;
                        v1 = ((word >> (sh + 1)) & 1u) ? v1 * 2.f : 0.f;
                    }
                    float2 o = make_float2(v0, v1);
                    *(float2*)(C + (size_t)row * DIM + col) = o;
                }
            }
        }
    }
}

// ---------------- final tiny GEMM: y = t @ W2[128,10] + b2 ----------------
__global__ __launch_bounds__(256) void mlp2_kernel(
    const float* __restrict__ T, const float* __restrict__ W2,
    const float* __restrict__ b2, float* __restrict__ Y)
{
    __shared__ float Wt[10 * 128];
    __shared__ float bsm[10];
    int tid = threadIdx.x;
    for (int f = tid; f < 1280; f += 256) {
        int k = f / 10, j = f % 10;
        Wt[j * 128 + k] = W2[f];
    }
    if (tid < 10) bsm[tid] = b2[tid];
    __syncthreads();
    int warp = tid >> 5, lane = tid & 31;
    int n = blockIdx.x * 8 + warp;
    if (n >= NN) return;
    float4 h = *(const float4*)(T + (size_t)n * 128 + lane * 4);
#pragma unroll
    for (int j = 0; j < 10; ++j) {
        float4 w = *(const float4*)(Wt + j * 128 + lane * 4);
        float s = h.x * w.x + h.y * w.y + h.z * w.z + h.w * w.w;
        s += __shfl_xor_sync(0xffffffffu, s, 16);
        s += __shfl_xor_sync(0xffffffffu, s, 8);
        s += __shfl_xor_sync(0xffffffffu, s, 4);
        s += __shfl_xor_sync(0xffffffffu, s, 2);
        s += __shfl_xor_sync(0xffffffffu, s, 1);
        if (lane == 0) Y[(size_t)n * 10 + j] = s + bsm[j];
    }
}

// ---------------- launch ----------------
extern "C" void kernel_launch(void* const* d_in, const int* in_sizes, int n_in,
                              void* d_out, int out_size)
{
    const float* x        = (const float*)d_in[0];
    const void*  ei_raw   = d_in[1];
    const float* ew       = (const float*)d_in[2];
    const float* W_lin_in = (const float*)d_in[3];
    const float* b_lin_in = (const float*)d_in[4];
    const float* W_agg_in = (const float*)d_in[5];
    const float* b_agg_in = (const float*)d_in[6];
    const float* W_lin_h  = (const float*)d_in[7];
    const float* b_lin_h  = (const float*)d_in[8];
    const float* W_agg_h  = (const float*)d_in[9];
    const float* b_agg_h  = (const float*)d_in[10];
    const float* W_mlp1   = (const float*)d_in[11];
    const float* b_mlp1   = (const float*)d_in[12];
    const float* W_mlp2   = (const float*)d_in[13];
    const float* b_mlp2   = (const float*)d_in[14];
    float* out   = (float*)d_out;
    float* out_h = out;
    float* out_y = out + (size_t)NN * 128;

    unsigned ka[3], kb[3];
    threefry2x32(0u, 42u, 0u, 0u, ka[0], kb[0]);
    threefry2x32(0u, 42u, 0u, 1u, ka[1], kb[1]);
    threefry2x32(0u, 42u, 0u, 2u, ka[2], kb[2]);

    float *p_h, *p_agg, *p_x1, *p_x2;
    unsigned* p_mask;
    cudaGetSymbolAddress((void**)&p_h,    g_h);
    cudaGetSymbolAddress((void**)&p_agg,  g_agg);
    cudaGetSymbolAddress((void**)&p_x1,   g_x1);
    cudaGetSymbolAddress((void**)&p_x2,   g_x2);
    cudaGetSymbolAddress((void**)&p_mask, g_mask);

    const int GBLK = (NN + 127) / 128;   // 391
    const float* Win[3] = { W_lin_in, W_lin_h, W_lin_h };
    const float* bin[3] = { b_lin_in, b_lin_h, b_lin_h };
    const float* Wag[3] = { W_agg_in, W_agg_h, W_agg_h };
    const float* bag[3] = { b_agg_in, b_agg_h, b_agg_h };
    float* outs[3] = { p_x1, p_x2, out_h };

    // launches 1-3: setup; launch 4 = first big GEMM (ncu captures launch #4)
    zero_cnt_kernel<<<(NN + 255) / 256, 256>>>();
    detect_kernel<<<1, 1024>>>((const unsigned*)ei_raw);
    unpack_count_kernel<<<(2 * NE + 255) / 256, 256>>>(ei_raw);
    tgemm_kernel<8, false, false, false><<<GBLK, 256>>>(
        x, nullptr, Win[0], bin[0], nullptr, p_h);          // <- profiled
    scan1_kernel<<<NBLKS, SCAN_BLK>>>();
    scan2_kernel<<<1, 64>>>();
    scan3_kernel<<<(NN + 255) / 256, 256>>>();
    fill_kernel<<<(NE + 255) / 256, 256>>>(ew);
    for (int l = 0; l < 3; ++l)
        mask_kernel<<<TOT / 256, 256>>>(ka[l], kb[l], l);

    const float* inp = x;
    for (int l = 0; l < 3; ++l) {
        if (l > 0)
            tgemm_kernel<8, false, false, false><<<GBLK, 256>>>(
                inp, nullptr, Win[l], bin[l], nullptr, p_h);
        aggregate_kernel<<<(NN + 7) / 8, 256>>>(p_h, p_agg);
        tgemm_kernel<16, true, true, true><<<GBLK, 256>>>(
            p_agg, inp, Wag[l], bag[l], p_mask + (size_t)l * MASK_WORDS, outs[l]);
        inp = outs[l];
    }
    tgemm_kernel<8, false, true, false><<<GBLK, 256>>>(
        out_h, nullptr, W_mlp1, b_mlp1, nullptr, p_agg);
    mlp2_kernel<<<(NN + 7) / 8, 256>>>(p_agg, W_mlp2, b_mlp2, out_y);
}